// round 15
// baseline (speedup 1.0000x reference)
#include <cuda_runtime.h>
#include <cuda_fp16.h>
#include <cstdint>

typedef unsigned int u32;

// Problem constants: B=2, N=2048, D=1024, H=16, DH=64.  M = B*N = 4096.
// Harness ptxas target is sm_100 (no 'a') -> tcgen05 unavailable; mma.sync only.

// ---------------- scratch (static device .bss; no allocations) ----------------
static __device__ __half g_Xh[4096 * 1024];
static __device__ __half g_Wqkvh[1024 * 3072];
static __device__ __half g_Wouth[1024 * 1024];
static __device__ __half g_QKVh[4096 * 3072];
static __device__ __half g_AO[4096 * 1024];

// ---------------- merged fp32 -> fp16 converts (one launch) ----------------
__global__ void convert_all(const float* __restrict__ x,
                            const float* __restrict__ wq,
                            const float* __restrict__ wo,
                            __half* __restrict__ xh,
                            __half* __restrict__ wqh,
                            __half* __restrict__ woh)
{
    const int n1 = 4096 * 1024 / 2;
    const int n2 = 1024 * 3072 / 2;
    const int n3 = 1024 * 1024 / 2;
    const int total = n1 + n2 + n3;
    for (int i = blockIdx.x * blockDim.x + threadIdx.x; i < total;
         i += gridDim.x * blockDim.x) {
        const float2* src;
        __half2* dst;
        int k;
        if (i < n1) {
            src = reinterpret_cast<const float2*>(x);
            dst = reinterpret_cast<__half2*>(xh);
            k = i;
        } else if (i < n1 + n2) {
            src = reinterpret_cast<const float2*>(wq);
            dst = reinterpret_cast<__half2*>(wqh);
            k = i - n1;
        } else {
            src = reinterpret_cast<const float2*>(wo);
            dst = reinterpret_cast<__half2*>(woh);
            k = i - n1 - n2;
        }
        float2 f = src[k];
        dst[k] = __floats2half2_rn(f.x, f.y);
    }
}

// ---------------- PTX helpers ----------------
__device__ __forceinline__ void ldsm4(u32& r0, u32& r1, u32& r2, u32& r3, u32 a)
{
    asm volatile("ldmatrix.sync.aligned.m8n8.x4.shared.b16 {%0,%1,%2,%3}, [%4];"
                 : "=r"(r0), "=r"(r1), "=r"(r2), "=r"(r3) : "r"(a));
}

__device__ __forceinline__ void ldsm4t(u32& r0, u32& r1, u32& r2, u32& r3, u32 a)
{
    asm volatile("ldmatrix.sync.aligned.m8n8.x4.trans.shared.b16 {%0,%1,%2,%3}, [%4];"
                 : "=r"(r0), "=r"(r1), "=r"(r2), "=r"(r3) : "r"(a));
}

__device__ __forceinline__ void mma16816(float* d, const u32* a, u32 b0, u32 b1)
{
    asm volatile(
        "mma.sync.aligned.m16n8k16.row.col.f32.f16.f16.f32 "
        "{%0,%1,%2,%3},{%4,%5,%6,%7},{%8,%9},{%0,%1,%2,%3};"
        : "+f"(d[0]), "+f"(d[1]), "+f"(d[2]), "+f"(d[3])
        : "r"(a[0]), "r"(a[1]), "r"(a[2]), "r"(a[3]), "r"(b0), "r"(b1));
}

__device__ __forceinline__ u32 ex2_f16x2(u32 a)
{
    u32 d;
    asm volatile("ex2.approx.f16x2 %0, %1;" : "=r"(d) : "r"(a));
    return d;
}

// swizzled byte offset, 128B rows (64 halves), c8 in 0..7
__device__ __forceinline__ u32 swzb(int r, int c8)
{
    return (u32)(((r << 6) + ((c8 ^ (r & 7)) << 3)) << 1);
}

// swizzled byte offset, 64B rows (32 halves), c8 in 0..3
__device__ __forceinline__ u32 swzb32(int r, int c8)
{
    return (u32)((r << 6) + ((c8 ^ ((r >> 1) & 3)) << 4));
}

// epilogue pair stores
__device__ __forceinline__ void store2(__half* p, float a, float b)
{
    *reinterpret_cast<__half2*>(p) = __floats2half2_rn(a, b);
}
__device__ __forceinline__ void store2(float* p, float a, float b)
{
    float2 v;
    v.x = a;
    v.y = b;
    *reinterpret_cast<float2*>(p) = v;
}

// ---------------- raw-PTX double-buffered GEMM ----------------
// BM=128, BN=128, BK=32. 128 threads, 4 warps (2x2), 64x64 warp tiles.
// Per slab per warp: 8 ldsm4t (B) + 8 ldsm4 (A) feed 64 HMMAs (1.0 wf/HMMA).
template <typename CT>
__global__ void __launch_bounds__(128)
gemm_raw(const __half* __restrict__ A, int lda,
         const __half* __restrict__ B, int ldb,
         CT* __restrict__ C, int ldc,
         int K, const float* __restrict__ bias)
{
    __shared__ __align__(16) char sm[32768];
    // layout: As[buf] at buf*8192 (128 rows x 64B, swzb32)
    //         Bs[buf] at 16384 + buf*8192, two 4096B blocks (32 rows x 128B, swzb)
    const u32 base = (u32)__cvta_generic_to_shared(sm);

    const int tid  = threadIdx.x;
    const int warp = tid >> 5;
    const int lane = tid & 31;
    const int wm   = warp >> 1;
    const int wn   = warp & 1;
    const int bm   = blockIdx.y * 128;
    const int bn   = blockIdx.x * 128;

    // staging coords: A 512 chunks (4/thread), B 512 chunks (4/thread)
    int ar[4], agc[4];
    u32 aoff[4];
    int brr[4], bgc[4];
    u32 boff[4];
#pragma unroll
    for (int j = 0; j < 4; j++) {
        int ia = tid + j * 128;
        ar[j]   = ia >> 2;
        agc[j]  = (ia & 3) * 8;
        aoff[j] = swzb32(ar[j], ia & 3);
        int ib = tid + j * 128;
        brr[j]  = ib >> 4;
        int nc  = ib & 15;
        bgc[j]  = nc * 8;
        boff[j] = (u32)((nc >> 3) * 4096) + swzb(brr[j], nc & 7);
    }

    float acc[4][8][4];
#pragma unroll
    for (int mt = 0; mt < 4; mt++) {
#pragma unroll
        for (int n8 = 0; n8 < 8; n8++) {
#pragma unroll
            for (int c = 0; c < 4; c++) {
                acc[mt][n8][c] = 0.f;
            }
        }
    }

    uint4 ra[4], rb[4];

    // prologue: slab 0 -> regs -> smem buf0
#pragma unroll
    for (int j = 0; j < 4; j++) {
        ra[j] = *reinterpret_cast<const uint4*>(&A[(size_t)(bm + ar[j]) * lda + agc[j]]);
        rb[j] = *reinterpret_cast<const uint4*>(&B[(size_t)brr[j] * ldb + bn + bgc[j]]);
    }
#pragma unroll
    for (int j = 0; j < 4; j++) {
        *reinterpret_cast<uint4*>(sm + aoff[j]) = ra[j];
        *reinterpret_cast<uint4*>(sm + 16384 + boff[j]) = rb[j];
    }
    __syncthreads();

    // A fragment address components (flash qf pattern)
    const int mm = lane >> 3;
    const int rr = lane & 7;
    const int arow_base = wm * 64 + rr + (mm & 1) * 8;
    const int ac8_base  = mm >> 1;

    const int NT = K / 32;
    for (int t = 0; t < NT; t++) {
        if (t + 1 < NT) {
            const int k0 = (t + 1) * 32;
#pragma unroll
            for (int j = 0; j < 4; j++) {
                ra[j] = *reinterpret_cast<const uint4*>(&A[(size_t)(bm + ar[j]) * lda + k0 + agc[j]]);
                rb[j] = *reinterpret_cast<const uint4*>(&B[(size_t)(k0 + brr[j]) * ldb + bn + bgc[j]]);
            }
        }

        const u32 abuf = base + (u32)((t & 1) * 8192);
        const u32 bbuf = base + 16384u + (u32)((t & 1) * 8192) + (u32)(wn * 4096);

        // B fragments: 8 n8-groups, full 32-k slab each (b0,b1 = k0-15; b2,b3 = k16-31)
        u32 bf[8][4];
#pragma unroll
        for (int n8 = 0; n8 < 8; n8++) {
            ldsm4t(bf[n8][0], bf[n8][1], bf[n8][2], bf[n8][3], bbuf + swzb(lane, n8));
        }

#pragma unroll
        for (int kc = 0; kc < 2; kc++) {
            u32 af[4][4];
#pragma unroll
            for (int mt = 0; mt < 4; mt++) {
                ldsm4(af[mt][0], af[mt][1], af[mt][2], af[mt][3],
                      abuf + swzb32(arow_base + mt * 16, kc * 2 + ac8_base));
            }
#pragma unroll
            for (int mt = 0; mt < 4; mt++) {
#pragma unroll
                for (int n8 = 0; n8 < 8; n8++) {
                    mma16816(acc[mt][n8], af[mt], bf[n8][2 * kc], bf[n8][2 * kc + 1]);
                }
            }
        }

        if (t + 1 < NT) {
            const int s = (t + 1) & 1;
#pragma unroll
            for (int j = 0; j < 4; j++) {
                *reinterpret_cast<uint4*>(sm + s * 8192 + aoff[j]) = ra[j];
                *reinterpret_cast<uint4*>(sm + 16384 + s * 8192 + boff[j]) = rb[j];
            }
            __syncthreads();
        }
    }

    // direct epilogue: bias + convert + paired stores
    const int erow = lane >> 2;
    const int ecol = (lane & 3) * 2;
#pragma unroll
    for (int mt = 0; mt < 4; mt++) {
        const int row0 = bm + wm * 64 + mt * 16 + erow;
#pragma unroll
        for (int n8 = 0; n8 < 8; n8++) {
            const int col = bn + wn * 64 + n8 * 8 + ecol;
            const float b0 = bias[col];
            const float b1 = bias[col + 1];
            store2(&C[(size_t)row0 * ldc + col],
                   acc[mt][n8][0] + b0, acc[mt][n8][1] + b1);
            store2(&C[(size_t)(row0 + 8) * ldc + col],
                   acc[mt][n8][2] + b0, acc[mt][n8][3] + b1);
        }
    }
}

// ---------------- fused flash attention v4 (round-13 winner, unchanged) ----------------
// BM=256 rows/CTA, 256 threads = 8 warps, 32 rows/warp (two 16-row m-tiles).
__global__ void __launch_bounds__(256, 1)
flash_kernel(const __half* __restrict__ QKV, __half* __restrict__ AO)
{
    __shared__ __align__(16) char smem_raw[32768];   // Q (transient) then K|V

    const u32 sbase = (u32)__cvta_generic_to_shared(smem_raw);
    const u32 qb = sbase;
    const u32 kb = sbase;
    const u32 vb = sbase + 16384u;

    const int tid  = threadIdx.x;
    const int warp = tid >> 5;
    const int lane = tid & 31;
    const int bh   = blockIdx.y;
    const int b    = bh >> 4;
    const int h    = bh & 15;
    const int mblk = blockIdx.x;

    const size_t bbase = (size_t)b * 2048 * 3072 + (size_t)h * 64;
    const __half* gQ = QKV + bbase + (size_t)mblk * 256 * 3072;
    const __half* gK = QKV + bbase + 1024;
    const __half* gV = QKV + bbase + 2048;
    __half* gO = AO + (size_t)b * 2048 * 1024 + (size_t)h * 64 + (size_t)mblk * 256 * 1024;

    const int pc8 = tid & 7;
    u32 poff[4];
    size_t pgo[4];
#pragma unroll
    for (int j = 0; j < 4; j++) {
        int pr = (tid >> 3) + j * 32;
        poff[j] = swzb(pr, pc8);
        pgo[j]  = (size_t)pr * 3072 + pc8 * 8;
    }

    for (int i = tid; i < 2048; i += 256) {
        int r = i >> 3;
        int c8 = i & 7;
        *reinterpret_cast<uint4*>(smem_raw + swzb(r, c8)) =
            *reinterpret_cast<const uint4*>(gQ + (size_t)r * 3072 + c8 * 8);
    }
    __syncthreads();

    const int wr = warp * 32;

    u32 qf[2][4][4];
    {
        const __half2 sc = __half2half2(__float2half(0.125f * 1.44269504f));
#pragma unroll
        for (int mt = 0; mt < 2; mt++) {
#pragma unroll
            for (int kc = 0; kc < 4; kc++) {
                int mm = lane >> 3;
                int rr = lane & 7;
                int row = wr + mt * 16 + rr + (mm & 1) * 8;
                int c8  = kc * 2 + (mm >> 1);
                ldsm4(qf[mt][kc][0], qf[mt][kc][1], qf[mt][kc][2], qf[mt][kc][3],
                      qb + swzb(row, c8));
#pragma unroll
                for (int r = 0; r < 4; r++) {
                    __half2 v = __hmul2(*reinterpret_cast<__half2*>(&qf[mt][kc][r]), sc);
                    qf[mt][kc][r] = *reinterpret_cast<u32*>(&v);
                }
            }
        }
    }
    __syncthreads();

#pragma unroll
    for (int j = 0; j < 4; j++) {
        *reinterpret_cast<uint4*>(smem_raw + poff[j]) =
            *reinterpret_cast<const uint4*>(gK + pgo[j]);
        *reinterpret_cast<uint4*>(smem_raw + 16384 + poff[j]) =
            *reinterpret_cast<const uint4*>(gV + pgo[j]);
    }
    __syncthreads();

    const u32 ONES = 0x3C003C00u;   // (1.0h, 1.0h)

    float oacc[2][8][4];
    float lacc[2][4];
#pragma unroll
    for (int mt = 0; mt < 2; mt++) {
#pragma unroll
        for (int c = 0; c < 4; c++) {
            lacc[mt][c] = 0.f;
        }
#pragma unroll
        for (int jo = 0; jo < 8; jo++) {
#pragma unroll
            for (int c = 0; c < 4; c++) {
                oacc[mt][jo][c] = 0.f;
            }
        }
    }

    for (int t = 0; t < 16; t++) {
        uint4 kr[4], vr[4];
        if (t + 1 < 16) {
            const __half* gk = gK + (size_t)(t + 1) * 128 * 3072;
            const __half* gv = gV + (size_t)(t + 1) * 128 * 3072;
#pragma unroll
            for (int j = 0; j < 4; j++) {
                kr[j] = *reinterpret_cast<const uint4*>(gk + pgo[j]);
                vr[j] = *reinterpret_cast<const uint4*>(gv + pgo[j]);
            }
        }

#pragma unroll
        for (int ig = 0; ig < 4; ig++) {
            float sacc[2][4][4];
#pragma unroll
            for (int mt = 0; mt < 2; mt++) {
#pragma unroll
                for (int jl = 0; jl < 4; jl++) {
#pragma unroll
                    for (int c = 0; c < 4; c++) {
                        sacc[mt][jl][c] = 0.f;
                    }
                }
            }

#pragma unroll
            for (int jl = 0; jl < 4; jl++) {
                int j = ig * 4 + jl;
#pragma unroll
                for (int ik = 0; ik < 2; ik++) {
                    int row = j * 8 + (lane & 7);
                    int c8  = (lane >> 3) + ik * 4;
                    u32 b0, b1, b2, b3;
                    ldsm4(b0, b1, b2, b3, kb + swzb(row, c8));
                    mma16816(sacc[0][jl], qf[0][2 * ik], b0, b1);
                    mma16816(sacc[0][jl], qf[0][2 * ik + 1], b2, b3);
                    mma16816(sacc[1][jl], qf[1][2 * ik], b0, b1);
                    mma16816(sacc[1][jl], qf[1][2 * ik + 1], b2, b3);
                }
            }

            u32 ph[2][4][2];
#pragma unroll
            for (int mt = 0; mt < 2; mt++) {
#pragma unroll
                for (int jl = 0; jl < 4; jl++) {
                    __half2 s01 = __floats2half2_rn(sacc[mt][jl][0], sacc[mt][jl][1]);
                    __half2 s23 = __floats2half2_rn(sacc[mt][jl][2], sacc[mt][jl][3]);
                    ph[mt][jl][0] = ex2_f16x2(*reinterpret_cast<u32*>(&s01));
                    ph[mt][jl][1] = ex2_f16x2(*reinterpret_cast<u32*>(&s23));
                }
            }

            u32 pa[2][4], pb[2][4];
#pragma unroll
            for (int mt = 0; mt < 2; mt++) {
                pa[mt][0] = ph[mt][0][0];
                pa[mt][1] = ph[mt][0][1];
                pa[mt][2] = ph[mt][1][0];
                pa[mt][3] = ph[mt][1][1];
                pb[mt][0] = ph[mt][2][0];
                pb[mt][1] = ph[mt][2][1];
                pb[mt][2] = ph[mt][3][0];
                pb[mt][3] = ph[mt][3][1];
                mma16816(lacc[mt], pa[mt], ONES, ONES);
                mma16816(lacc[mt], pb[mt], ONES, ONES);
            }

#pragma unroll
            for (int jo = 0; jo < 8; jo++) {
                int row = ig * 32 + lane;
                u32 b0, b1, b2, b3;
                ldsm4t(b0, b1, b2, b3, vb + swzb(row, jo));
#pragma unroll
                for (int mt = 0; mt < 2; mt++) {
                    mma16816(oacc[mt][jo], pa[mt], b0, b1);
                    mma16816(oacc[mt][jo], pb[mt], b2, b3);
                }
            }
        }
        __syncthreads();

        if (t + 1 < 16) {
#pragma unroll
            for (int j = 0; j < 4; j++) {
                *reinterpret_cast<uint4*>(smem_raw + poff[j]) = kr[j];
                *reinterpret_cast<uint4*>(smem_raw + 16384 + poff[j]) = vr[j];
            }
            __syncthreads();
        }
    }

#pragma unroll
    for (int mt = 0; mt < 2; mt++) {
        const float inv0 = 1.f / lacc[mt][0];
        const float inv1 = 1.f / lacc[mt][2];
        const int r0 = wr + mt * 16 + (lane >> 2);
        const int cb = (lane & 3) * 2;
#pragma unroll
        for (int jo = 0; jo < 8; jo++) {
            __half2 h0 = __floats2half2_rn(oacc[mt][jo][0] * inv0, oacc[mt][jo][1] * inv0);
            __half2 h1 = __floats2half2_rn(oacc[mt][jo][2] * inv1, oacc[mt][jo][3] * inv1);
            *reinterpret_cast<__half2*>(gO + (size_t)r0 * 1024 + jo * 8 + cb) = h0;
            *reinterpret_cast<__half2*>(gO + (size_t)(r0 + 8) * 1024 + jo * 8 + cb) = h1;
        }
    }
}

// ---------------- launcher ----------------
extern "C" void kernel_launch(void* const* d_in, const int* in_sizes, int n_in,
                              void* d_out, int out_size)
{
    (void)in_sizes;
    (void)n_in;
    (void)out_size;
    const float* x     = (const float*)d_in[0];
    const float* W_qkv = (const float*)d_in[1];
    const float* b_qkv = (const float*)d_in[2];
    const float* W_out = (const float*)d_in[3];
    const float* b_out = (const float*)d_in[4];
    float* out = (float*)d_out;

    __half* Xh;
    __half* Wq;
    __half* Wo;
    __half* QKV;
    __half* AO;
    cudaGetSymbolAddress((void**)&Xh,  g_Xh);
    cudaGetSymbolAddress((void**)&Wq,  g_Wqkvh);
    cudaGetSymbolAddress((void**)&Wo,  g_Wouth);
    cudaGetSymbolAddress((void**)&QKV, g_QKVh);
    cudaGetSymbolAddress((void**)&AO,  g_AO);

    // converts (single merged launch)
    convert_all<<<2048, 256>>>(x, W_qkv, W_out, Xh, Wq, Wo);

    // 1) QKV = Xh @ Wq (+b_qkv), fp16 [4096, 3072]
    gemm_raw<__half><<<dim3(24, 32, 1), 128>>>(
        Xh, 1024, Wq, 3072, QKV, 3072, 1024, b_qkv);

    // 2) fused flash attention -> AO fp16 [4096, 1024]; 256-row m-blocks
    flash_kernel<<<dim3(8, 32, 1), 256>>>(QKV, AO);

    // 3) out = AO @ Wo + b_out, fp32
    gemm_raw<float><<<dim3(8, 32, 1), 128>>>(
        AO, 1024, Wo, 1024, out, 1024, 1024, b_out);
}